// round 1
// baseline (speedup 1.0000x reference)
#include <cuda_runtime.h>
#include <cuda_bf16.h>

#define BATCH 32
#define SEQ   2048
#define EDIM  128
#define HVOC  500000
#define HBASE 257
#define NPOS  (BATCH * SEQ)

// One warp per (b, s) position. Each lane handles 4 floats (float4) of the
// 128-dim embedding. 6 independent gathers per warp -> MLP=6.
__global__ __launch_bounds__(256) void ngram_embed_kernel(
    const int* __restrict__ tokens,     // (B, S) int32
    const float* __restrict__ tables,   // (6, V, D) fp32
    float* __restrict__ out)            // (B, S, D) fp32
{
    const int gwarp = (blockIdx.x * blockDim.x + threadIdx.x) >> 5;
    const int lane  = threadIdx.x & 31;
    if (gwarp >= NPOS) return;

    const int b = gwarp >> 11;       // / SEQ
    const int s = gwarp & (SEQ - 1); // % SEQ

    const int* __restrict__ trow = tokens + (long)b * SEQ;
    const int x0 = __ldg(&trow[s]);

    // Incremental rolling hash. After j multiply-add steps the value equals
    // the reference hash for n = j+1. Record indices for n in {3..8} (j in {2..7}).
    // Reference semantics: for s >= n-1 use hash h, else use raw byte x0.
    int idx[6];
    int h = x0;
#pragma unroll
    for (int j = 1; j <= 7; j++) {
        const int prev = (s - j >= 0) ? __ldg(&trow[s - j]) : 0;
        h = (h * HBASE + prev) % HVOC;   // < 257*500000 + 255 < 2^31, safe
        if (j >= 2) {
            // n = j+1, condition s >= n-1  <=>  s >= j
            idx[j - 2] = (s >= j) ? h : x0;
        }
    }

    // 6 independent 512B gathers, one float4 per lane, accumulate.
    float4 acc = make_float4(0.f, 0.f, 0.f, 0.f);
#pragma unroll
    for (int k = 0; k < 6; k++) {
        const float4* __restrict__ row = reinterpret_cast<const float4*>(
            tables + ((long)k * HVOC + idx[k]) * EDIM);
        const float4 v = __ldg(&row[lane]);
        acc.x += v.x; acc.y += v.y; acc.z += v.z; acc.w += v.w;
    }

    const float inv6 = 1.0f / 6.0f;
    acc.x *= inv6; acc.y *= inv6; acc.z *= inv6; acc.w *= inv6;

    reinterpret_cast<float4*>(out + (long)gwarp * EDIM)[lane] = acc;
}

extern "C" void kernel_launch(void* const* d_in, const int* in_sizes, int n_in,
                              void* d_out, int out_size) {
    const int*   tokens = (const int*)d_in[0];
    const float* tables = (const float*)d_in[1];
    float*       out    = (float*)d_out;

    const int threads = 256;                  // 8 warps = 8 positions per block
    const int warps_per_block = threads / 32;
    const int blocks = (NPOS + warps_per_block - 1) / warps_per_block;
    ngram_embed_kernel<<<blocks, threads>>>(tokens, tables, out);
}